// round 10
// baseline (speedup 1.0000x reference)
#include <cuda_runtime.h>
#include <math.h>
#include <stdint.h>

#define NN 100000
#define EE 1600000
#define DIN 256
#define DH 64
#define DOUT 3
#define NG 64
#define BN_EPSF 1e-5f

#define SCAN_ELEMS 1024
#define NBLK ((NN + SCAN_ELEMS - 1) / SCAN_ELEMS)   // 98

// ---------------- scratch (device globals; no allocation allowed) -------------
__device__ int    d_deg[NN];
__device__ __align__(16) float d_dinv[NN];
__device__ int    d_rowoff[NN + 1];
__device__ int    d_fillpos[NN];
__device__ int    d_blocksum[NBLK];
__device__ int    d_blockoff[NBLK];
__device__ int    d_csrc[EE];
__device__ __align__(16) float d_bufT[(size_t)NN * DH];
__device__ __align__(16) float d_bufA[(size_t)NN * DH];
__device__ __align__(16) float d_h3t[NN * DOUT + 4];
__device__ __align__(16) float d_h3[NN * DOUT + 4];
__device__ float  d_sum1[DH], d_sq1[DH], d_sum2[DH], d_sq2[DH];
__device__ float  d_pool[NG * 4];
__device__ __align__(16) uint2 d_W1hl[64 * DIN];   // [n][k] tf32 (hi,lo)
__device__ __align__(16) uint2 d_W2hl[64 * DH];

// ---------------- structure build ---------------------------------------------
__global__ void k_init() {
    int i = blockIdx.x * blockDim.x + threadIdx.x;
    if (i < NN) d_deg[i] = 1;
    if (i < DH) { d_sum1[i] = 0.f; d_sq1[i] = 0.f; d_sum2[i] = 0.f; d_sq2[i] = 0.f; }
    if (i < NG * 4) d_pool[i] = 0.f;
}

__global__ void k_hist(const int* __restrict__ ei) {
    int e = blockIdx.x * blockDim.x + threadIdx.x;
    if (e < EE) atomicAdd(&d_deg[ei[EE + e]], 1);
}

__global__ void k_partial() {
    int t = threadIdx.x;
    int idx = blockIdx.x * SCAN_ELEMS + t * 4;
    int s = 0;
    if (idx < NN) {
        int4 d = *(const int4*)(d_deg + idx);
        s = d.x + d.y + d.z + d.w - 4;
        float4 r;
        r.x = rsqrtf((float)d.x);
        r.y = rsqrtf((float)d.y);
        r.z = rsqrtf((float)d.z);
        r.w = rsqrtf((float)d.w);
        *(float4*)(d_dinv + idx) = r;
    }
    __shared__ int sh[8];
#pragma unroll
    for (int o = 16; o; o >>= 1) s += __shfl_down_sync(0xffffffffu, s, o);
    if ((t & 31) == 0) sh[t >> 5] = s;
    __syncthreads();
    if (t < 32) {
        int v = (t < 8) ? sh[t] : 0;
#pragma unroll
        for (int o = 4; o; o >>= 1) v += __shfl_down_sync(0xffffffffu, v, o);
        if (t == 0) d_blocksum[blockIdx.x] = v;
    }
}

__global__ void k_scanblock() {
    __shared__ int sh[128];
    int t = threadIdx.x;
    int v = (t < NBLK) ? d_blocksum[t] : 0;
    sh[t] = v;
    __syncthreads();
#pragma unroll
    for (int off = 1; off < 128; off <<= 1) {
        int a = (t >= off) ? sh[t - off] : 0;
        __syncthreads();
        sh[t] += a;
        __syncthreads();
    }
    if (t < NBLK) d_blockoff[t] = sh[t] - v;
    if (t == 127) d_rowoff[NN] = sh[127];
}

__global__ void k_scatter() {
    __shared__ int tsum[256];
    int t = threadIdx.x;
    int idx = blockIdx.x * SCAN_ELEMS + t * 4;
    int v0 = 0, v1 = 0, v2 = 0, v3 = 0;
    if (idx < NN) {
        int4 d = *(const int4*)(d_deg + idx);
        v0 = d.x - 1; v1 = d.y - 1; v2 = d.z - 1; v3 = d.w - 1;
    }
    int s = v0 + v1 + v2 + v3;
    tsum[t] = s;
    __syncthreads();
#pragma unroll
    for (int off = 1; off < 256; off <<= 1) {
        int a = (t >= off) ? tsum[t - off] : 0;
        __syncthreads();
        tsum[t] += a;
        __syncthreads();
    }
    if (idx < NN) {
        int run = d_blockoff[blockIdx.x] + tsum[t] - s;
        int4 ro = make_int4(run, run + v0, run + v0 + v1, run + v0 + v1 + v2);
        *(int4*)(d_rowoff  + idx) = ro;
        *(int4*)(d_fillpos + idx) = ro;
    }
}

__global__ void k_fill(const int* __restrict__ ei) {
    int e = blockIdx.x * blockDim.x + threadIdx.x;
    if (e >= EE) return;
    int s = ei[e];
    int d = ei[EE + e];
    int p = atomicAdd(&d_fillpos[d], 1);
    d_csrc[p] = s;
}

// ---------------- tf32 helpers --------------------------------------------------
__device__ __forceinline__ uint32_t f2tf32(float x) {
    uint32_t r;
    asm("cvt.rna.tf32.f32 %0, %1;" : "=r"(r) : "f"(x));
    return r;
}
__device__ __forceinline__ uint2 split_tf32(float x) {
    uint32_t hi = f2tf32(x);
    uint32_t lo = f2tf32(x - __uint_as_float(hi));
    return make_uint2(hi, lo);
}
__device__ __forceinline__ void mma_tf32(float* c, const uint32_t* a,
                                         uint32_t b0, uint32_t b1) {
    asm volatile(
        "mma.sync.aligned.m16n8k8.row.col.f32.tf32.tf32.f32 "
        "{%0,%1,%2,%3},{%4,%5,%6,%7},{%8,%9},{%0,%1,%2,%3};"
        : "+f"(c[0]), "+f"(c[1]), "+f"(c[2]), "+f"(c[3])
        : "r"(a[0]), "r"(a[1]), "r"(a[2]), "r"(a[3]), "r"(b0), "r"(b1));
}

// pre-split W[K][64] -> Whl[n][k] (tf32 hi/lo)
__global__ void k_prepW(const float* __restrict__ W, uint2* __restrict__ out, int K) {
    int idx = blockIdx.x * blockDim.x + threadIdx.x;
    if (idx >= K * 64) return;
    int k = idx >> 6, n = idx & 63;
    out[n * K + k] = split_tf32(W[idx]);
}

// ---------------- tensor-core GEMM: [nrows,K] @ [K,64] -> [nrows,64] -----------
// Block: 128 rows x 64 cols, 8 warps (16 rows each). 3xTF32 compensated.
// All cvts hoisted: A split at staging, W pre-split globally.
#define KC 16
#define SPADU 20       // uint2 row stride: 40 banks == 8 mod 32 -> conflict-free frags
template <int K, bool BN>
__global__ void __launch_bounds__(256)
k_gemmTC(const float* __restrict__ A, const uint2* __restrict__ Whl,
         float* __restrict__ out, int nrows,
         const float* __restrict__ sumv, const float* __restrict__ sqv,
         const float* __restrict__ g, const float* __restrict__ be)
{
    __shared__ __align__(16) uint2 sA[128 * SPADU];   // [row][k] (hi,lo)
    __shared__ __align__(16) uint2 sB[64 * SPADU];    // [n][k]   (hi,lo)
    __shared__ float bnA[64], bnB[64];

    int tid  = threadIdx.x;
    int lane = tid & 31;
    int wid  = tid >> 5;
    int lg = lane >> 2;
    int lk = lane & 3;
    int row0 = blockIdx.x * 128;
    int wrow = wid * 16;

    if (BN) {
        if (tid < 64) {
            float mu  = sumv[tid] * (1.0f / NN);
            float var = sqv[tid] * (1.0f / NN) - mu * mu;
            float a = g[tid] * rsqrtf(var + BN_EPSF);
            bnA[tid] = a;
            bnB[tid] = be[tid] - mu * a;
        }
        __syncthreads();
    }

    float C[8][4];
#pragma unroll
    for (int n = 0; n < 8; n++)
#pragma unroll
        for (int j = 0; j < 4; j++) C[n][j] = 0.f;

    for (int kc = 0; kc < K; kc += KC) {
        // stage A: 128 rows x 16 k = 512 float4 (2/thread), split to hi/lo
#pragma unroll
        for (int it = 0; it < 2; it++) {
            int f4 = it * 256 + tid;
            int r  = f4 >> 2;
            int c4 = (f4 & 3) * 4;
            float4 v = make_float4(0.f, 0.f, 0.f, 0.f);
            if (row0 + r < nrows)
                v = *(const float4*)(A + (size_t)(row0 + r) * K + kc + c4);
            if (BN) {
                int c = kc + c4;
                v.x = fmaxf(fmaf(v.x, bnA[c + 0], bnB[c + 0]), 0.f);
                v.y = fmaxf(fmaf(v.y, bnA[c + 1], bnB[c + 1]), 0.f);
                v.z = fmaxf(fmaf(v.z, bnA[c + 2], bnB[c + 2]), 0.f);
                v.w = fmaxf(fmaf(v.w, bnA[c + 3], bnB[c + 3]), 0.f);
            }
            uint2* p = sA + r * SPADU + c4;
            p[0] = split_tf32(v.x);
            p[1] = split_tf32(v.y);
            p[2] = split_tf32(v.z);
            p[3] = split_tf32(v.w);
        }
        // stage B: 64 n x 16 k uint2 = 1024 (4/thread), pure copy
#pragma unroll
        for (int it = 0; it < 4; it++) {
            int idx = it * 256 + tid;
            int n = idx >> 4;
            int k = idx & 15;
            sB[n * SPADU + k] = Whl[n * K + kc + k];
        }
        __syncthreads();

#pragma unroll
        for (int kk = 0; kk < KC; kk += 8) {
            uint2 a0 = sA[(wrow + lg)     * SPADU + kk + lk];
            uint2 a1 = sA[(wrow + lg + 8) * SPADU + kk + lk];
            uint2 a2 = sA[(wrow + lg)     * SPADU + kk + lk + 4];
            uint2 a3 = sA[(wrow + lg + 8) * SPADU + kk + lk + 4];
            uint32_t ahi[4] = {a0.x, a1.x, a2.x, a3.x};
            uint32_t alo[4] = {a0.y, a1.y, a2.y, a3.y};
#pragma unroll
            for (int nt = 0; nt < 8; nt++) {
                uint2 b0 = sB[(nt * 8 + lg) * SPADU + kk + lk];
                uint2 b1 = sB[(nt * 8 + lg) * SPADU + kk + lk + 4];
                mma_tf32(C[nt], alo, b0.x, b1.x);
                mma_tf32(C[nt], ahi, b0.y, b1.y);
                mma_tf32(C[nt], ahi, b0.x, b1.x);
            }
        }
        __syncthreads();
    }

    int r0 = row0 + wrow + lg;
    int r1 = r0 + 8;
#pragma unroll
    for (int nt = 0; nt < 8; nt++) {
        int col = nt * 8 + 2 * lk;
        if (r0 < nrows)
            *(float2*)(out + (size_t)r0 * 64 + col) = make_float2(C[nt][0], C[nt][1]);
        if (r1 < nrows)
            *(float2*)(out + (size_t)r1 * 64 + col) = make_float2(C[nt][2], C[nt][3]);
    }
}

// ---------------- aggregation (pull, CSR by dst) + bias + fused BN stats -------
__global__ void k_agg64(const float* __restrict__ ht, const float* __restrict__ bias,
                        float* __restrict__ out,
                        float* __restrict__ sumv, float* __restrict__ sqv)
{
    __shared__ float s_s[8 * 64];
    __shared__ float s_q[8 * 64];
    int warp = (blockIdx.x * blockDim.x + threadIdx.x) >> 5;
    int w    = threadIdx.x >> 5;
    int lane = threadIdx.x & 31;
    int c0   = lane * 2;
    float acc0 = 0.f, acc1 = 0.f;
    if (warp < NN) {
        const int i = warp;
        float di = d_dinv[i];
        float2 sv = *(const float2*)(ht + i * 64 + c0);
        acc0 = di * di * sv.x;
        acc1 = di * di * sv.y;
        int e0 = d_rowoff[i], e1 = d_rowoff[i + 1];
        for (int j0 = e0; j0 < e1; j0 += 32) {
            int j = j0 + lane;
            int src = 0; float dv = 0.f;
            if (j < e1) { src = d_csrc[j]; dv = __ldg(&d_dinv[src]); }
            int cnt = min(32, e1 - j0);
#pragma unroll 4
            for (int k = 0; k < cnt; k++) {
                int   sk = __shfl_sync(0xffffffffu, src, k);
                float wk = __shfl_sync(0xffffffffu, dv, k) * di;
                float2 hv = __ldg((const float2*)(ht + sk * 64 + c0));
                acc0 = fmaf(wk, hv.x, acc0);
                acc1 = fmaf(wk, hv.y, acc1);
            }
        }
        acc0 += bias[c0];
        acc1 += bias[c0 + 1];
        *(float2*)(out + i * 64 + c0) = make_float2(acc0, acc1);
    }
    s_s[w * 64 + c0]     = acc0;
    s_s[w * 64 + c0 + 1] = acc1;
    s_q[w * 64 + c0]     = acc0 * acc0;
    s_q[w * 64 + c0 + 1] = acc1 * acc1;
    __syncthreads();
    if (threadIdx.x < 64) {
        float ss = 0.f, qs = 0.f;
#pragma unroll
        for (int r = 0; r < 8; r++) {
            ss += s_s[r * 64 + threadIdx.x];
            qs += s_q[r * 64 + threadIdx.x];
        }
        atomicAdd(&sumv[threadIdx.x], ss);
        atomicAdd(&sqv[threadIdx.x], qs);
    }
}

// ---------------- layer 3: BN+ReLU inline, [N,64]@[64,3] -----------------------
__global__ void k_gemm3(const float* __restrict__ h, const float* __restrict__ W3,
                        float* __restrict__ out,
                        const float* __restrict__ sumv, const float* __restrict__ sqv,
                        const float* __restrict__ g, const float* __restrict__ be)
{
    __shared__ float wsh[DH * DOUT];
    __shared__ float bnA[64], bnB[64];
    if (threadIdx.x < DH * DOUT) wsh[threadIdx.x] = W3[threadIdx.x];
    if (threadIdx.x < 64) {
        float mu  = sumv[threadIdx.x] * (1.0f / NN);
        float var = sqv[threadIdx.x] * (1.0f / NN) - mu * mu;
        float a = g[threadIdx.x] * rsqrtf(var + BN_EPSF);
        bnA[threadIdx.x] = a;
        bnB[threadIdx.x] = be[threadIdx.x] - mu * a;
    }
    __syncthreads();
    int i = blockIdx.x * blockDim.x + threadIdx.x;
    if (i >= NN) return;
    float a0 = 0.f, a1 = 0.f, a2 = 0.f;
    const float4* hp = (const float4*)(h + (size_t)i * DH);
#pragma unroll
    for (int q4 = 0; q4 < 16; q4++) {
        float4 v = hp[q4];
        int k = q4 * 4;
        float e0 = fmaxf(fmaf(v.x, bnA[k + 0], bnB[k + 0]), 0.f);
        float e1 = fmaxf(fmaf(v.y, bnA[k + 1], bnB[k + 1]), 0.f);
        float e2 = fmaxf(fmaf(v.z, bnA[k + 2], bnB[k + 2]), 0.f);
        float e3 = fmaxf(fmaf(v.w, bnA[k + 3], bnB[k + 3]), 0.f);
        a0 = fmaf(e0, wsh[(k + 0) * 3 + 0], a0); a1 = fmaf(e0, wsh[(k + 0) * 3 + 1], a1); a2 = fmaf(e0, wsh[(k + 0) * 3 + 2], a2);
        a0 = fmaf(e1, wsh[(k + 1) * 3 + 0], a0); a1 = fmaf(e1, wsh[(k + 1) * 3 + 1], a1); a2 = fmaf(e1, wsh[(k + 1) * 3 + 2], a2);
        a0 = fmaf(e2, wsh[(k + 2) * 3 + 0], a0); a1 = fmaf(e2, wsh[(k + 2) * 3 + 1], a1); a2 = fmaf(e2, wsh[(k + 2) * 3 + 2], a2);
        a0 = fmaf(e3, wsh[(k + 3) * 3 + 0], a0); a1 = fmaf(e3, wsh[(k + 3) * 3 + 1], a1); a2 = fmaf(e3, wsh[(k + 3) * 3 + 2], a2);
    }
    out[i * 3 + 0] = a0; out[i * 3 + 1] = a1; out[i * 3 + 2] = a2;
}

__global__ void k_agg3(const float* __restrict__ ht, const float* __restrict__ b3,
                       float* __restrict__ out)
{
    int i = blockIdx.x * blockDim.x + threadIdx.x;
    if (i >= NN) return;
    float di = d_dinv[i], ws = di * di;
    float a0 = ws * ht[i * 3 + 0];
    float a1 = ws * ht[i * 3 + 1];
    float a2 = ws * ht[i * 3 + 2];
    int e1 = d_rowoff[i + 1];
    for (int j = d_rowoff[i]; j < e1; j++) {
        int s = d_csrc[j];
        float w = __ldg(&d_dinv[s]) * di;
        a0 = fmaf(w, ht[s * 3 + 0], a0);
        a1 = fmaf(w, ht[s * 3 + 1], a1);
        a2 = fmaf(w, ht[s * 3 + 2], a2);
    }
    out[i * 3 + 0] = a0 + b3[0];
    out[i * 3 + 1] = a1 + b3[1];
    out[i * 3 + 2] = a2 + b3[2];
}

// ---------------- pooling + log_softmax ----------------------------------------
__global__ void k_pool(const float* __restrict__ h3, const int* __restrict__ batch)
{
    __shared__ float sh[NG * 4];
    if (threadIdx.x < NG * 4) sh[threadIdx.x] = 0.f;
    __syncthreads();
    int i = blockIdx.x * blockDim.x + threadIdx.x;
    if (i < NN) {
        int g = batch[i];
        atomicAdd(&sh[g * 4 + 0], h3[i * 3 + 0]);
        atomicAdd(&sh[g * 4 + 1], h3[i * 3 + 1]);
        atomicAdd(&sh[g * 4 + 2], h3[i * 3 + 2]);
        atomicAdd(&sh[g * 4 + 3], 1.0f);
    }
    __syncthreads();
    if (threadIdx.x < NG * 4 && sh[threadIdx.x] != 0.f)
        atomicAdd(&d_pool[threadIdx.x], sh[threadIdx.x]);
}

__global__ void k_final(float* __restrict__ out)
{
    int g = threadIdx.x;
    if (g >= NG) return;
    float cnt = fmaxf(d_pool[g * 4 + 3], 1.0f);
    float v0 = d_pool[g * 4 + 0] / cnt;
    float v1 = d_pool[g * 4 + 1] / cnt;
    float v2 = d_pool[g * 4 + 2] / cnt;
    float m = fmaxf(v0, fmaxf(v1, v2));
    float l = m + logf(expf(v0 - m) + expf(v1 - m) + expf(v2 - m));
    out[g * 3 + 0] = v0 - l;
    out[g * 3 + 1] = v1 - l;
    out[g * 3 + 2] = v2 - l;
}

// ---------------- launch --------------------------------------------------------
extern "C" void kernel_launch(void* const* d_in, const int* in_sizes, int n_in,
                              void* d_out, int out_size)
{
    const float* x    = (const float*)d_in[0];
    const int*   ei   = (const int*)d_in[1];
    const int*   batch= (const int*)d_in[2];
    const float* W1   = (const float*)d_in[3];
    const float* b1   = (const float*)d_in[4];
    const float* g1   = (const float*)d_in[5];
    const float* be1  = (const float*)d_in[6];
    const float* W2   = (const float*)d_in[7];
    const float* b2   = (const float*)d_in[8];
    const float* g2   = (const float*)d_in[9];
    const float* be2  = (const float*)d_in[10];
    const float* W3   = (const float*)d_in[11];
    const float* b3   = (const float*)d_in[12];
    float* out = (float*)d_out;

    float *bufT, *bufA, *h3t, *h3, *sum1, *sq1, *sum2, *sq2;
    uint2 *w1hl, *w2hl;
    cudaGetSymbolAddress((void**)&bufT, d_bufT);
    cudaGetSymbolAddress((void**)&bufA, d_bufA);
    cudaGetSymbolAddress((void**)&h3t,  d_h3t);
    cudaGetSymbolAddress((void**)&h3,   d_h3);
    cudaGetSymbolAddress((void**)&sum1, d_sum1);
    cudaGetSymbolAddress((void**)&sq1,  d_sq1);
    cudaGetSymbolAddress((void**)&sum2, d_sum2);
    cudaGetSymbolAddress((void**)&sq2,  d_sq2);
    cudaGetSymbolAddress((void**)&w1hl, d_W1hl);
    cudaGetSymbolAddress((void**)&w2hl, d_W2hl);

    static cudaStream_t s2 = 0;
    static cudaEvent_t evFork = 0, evJoin = 0;
    if (s2 == 0) {
        cudaStreamCreateWithFlags(&s2, cudaStreamNonBlocking);
        cudaEventCreateWithFlags(&evFork, cudaEventDisableTiming);
        cudaEventCreateWithFlags(&evJoin, cudaEventDisableTiming);
    }

    const int TB = 256;
    int gN = (NN + TB - 1) / TB;
    int gE = (EE + TB - 1) / TB;
    int gTC = (NN + 127) / 128;

    // fork: s2 runs W prep + GEMM1 overlapped with the structure build
    cudaEventRecord(evFork, 0);
    cudaStreamWaitEvent(s2, evFork, 0);

    k_init<<<gN, TB>>>();                                            // 1
    k_prepW<<<(DIN * 64 + TB - 1) / TB, TB, 0, s2>>>(W1, w1hl, DIN); // 2
    k_prepW<<<(DH * 64 + TB - 1) / TB, TB, 0, s2>>>(W2, w2hl, DH);   // 3
    k_gemmTC<DIN, false><<<gTC, 256, 0, s2>>>(x, w1hl, bufT, NN,     // 4 (ncu slot)
                                              0, 0, 0, 0);
    cudaEventRecord(evJoin, s2);

    k_hist<<<gE, TB>>>(ei);
    k_partial<<<NBLK, 256>>>();
    k_scanblock<<<1, 128>>>();
    k_scatter<<<NBLK, 256>>>();
    k_fill<<<gE, TB>>>(ei);

    cudaStreamWaitEvent(0, evJoin, 0);

    // layer 1 aggregation (+bias +BN stats)
    k_agg64<<<(NN * 32 + TB - 1) / TB, TB>>>(bufT, b1, bufA, sum1, sq1);

    // layer 2: tensor-core GEMM, BN+ReLU fused into A staging
    k_gemmTC<DH, true><<<gTC, 256>>>(bufA, w2hl, bufT, NN, sum1, sq1, g1, be1);
    k_agg64<<<(NN * 32 + TB - 1) / TB, TB>>>(bufT, b2, bufA, sum2, sq2);

    // layer 3
    k_gemm3<<<gN, TB>>>(bufA, W3, h3t, sum2, sq2, g2, be2);
    k_agg3<<<gN, TB>>>(h3t, b3, h3);
    k_pool<<<gN, TB>>>(h3, batch);
    k_final<<<1, 64>>>(out);
}

// round 11
// speedup vs baseline: 1.0771x; 1.0771x over previous
#include <cuda_runtime.h>
#include <math.h>
#include <stdint.h>

#define NN 100000
#define EE 1600000
#define DIN 256
#define DH 64
#define DOUT 3
#define NG 64
#define BN_EPSF 1e-5f

#define SCAN_ELEMS 1024
#define NBLK ((NN + SCAN_ELEMS - 1) / SCAN_ELEMS)   // 98

// ---------------- scratch (device globals; no allocation allowed) -------------
__device__ int    d_deg[NN];
__device__ __align__(16) float d_dinv[NN];
__device__ int    d_rowoff[NN + 1];
__device__ int    d_fillpos[NN];
__device__ int    d_blocksum[NBLK];
__device__ int    d_blockoff[NBLK];
__device__ int    d_csrc[EE];
__device__ __align__(16) float d_bufT[(size_t)NN * DH];
__device__ __align__(16) float d_bufA[(size_t)NN * DH];
__device__ __align__(16) float d_h3t[NN * DOUT + 4];
__device__ __align__(16) float d_h3[NN * DOUT + 4];
__device__ float  d_sum1[DH], d_sq1[DH], d_sum2[DH], d_sq2[DH];
__device__ float  d_pool[NG * 4];
__device__ __align__(16) uint2 d_W1hl[64 * DIN];   // [n][k] tf32 (hi,lo)
__device__ __align__(16) uint2 d_W2hl[64 * DH];

// ---------------- structure build ---------------------------------------------
__global__ void k_init() {
    int i = blockIdx.x * blockDim.x + threadIdx.x;
    if (i < NN) d_deg[i] = 1;
    if (i < DH) { d_sum1[i] = 0.f; d_sq1[i] = 0.f; d_sum2[i] = 0.f; d_sq2[i] = 0.f; }
    if (i < NG * 4) d_pool[i] = 0.f;
}

__global__ void k_hist(const int* __restrict__ ei) {
    int e = blockIdx.x * blockDim.x + threadIdx.x;
    if (e < EE) atomicAdd(&d_deg[ei[EE + e]], 1);
}

__global__ void k_partial() {
    int t = threadIdx.x;
    int idx = blockIdx.x * SCAN_ELEMS + t * 4;
    int s = 0;
    if (idx < NN) {
        int4 d = *(const int4*)(d_deg + idx);
        s = d.x + d.y + d.z + d.w - 4;
        float4 r;
        r.x = rsqrtf((float)d.x);
        r.y = rsqrtf((float)d.y);
        r.z = rsqrtf((float)d.z);
        r.w = rsqrtf((float)d.w);
        *(float4*)(d_dinv + idx) = r;
    }
    __shared__ int sh[8];
#pragma unroll
    for (int o = 16; o; o >>= 1) s += __shfl_down_sync(0xffffffffu, s, o);
    if ((t & 31) == 0) sh[t >> 5] = s;
    __syncthreads();
    if (t < 32) {
        int v = (t < 8) ? sh[t] : 0;
#pragma unroll
        for (int o = 4; o; o >>= 1) v += __shfl_down_sync(0xffffffffu, v, o);
        if (t == 0) d_blocksum[blockIdx.x] = v;
    }
}

__global__ void k_scanblock() {
    __shared__ int sh[128];
    int t = threadIdx.x;
    int v = (t < NBLK) ? d_blocksum[t] : 0;
    sh[t] = v;
    __syncthreads();
#pragma unroll
    for (int off = 1; off < 128; off <<= 1) {
        int a = (t >= off) ? sh[t - off] : 0;
        __syncthreads();
        sh[t] += a;
        __syncthreads();
    }
    if (t < NBLK) d_blockoff[t] = sh[t] - v;
    if (t == 127) d_rowoff[NN] = sh[127];
}

__global__ void k_scatter() {
    __shared__ int tsum[256];
    int t = threadIdx.x;
    int idx = blockIdx.x * SCAN_ELEMS + t * 4;
    int v0 = 0, v1 = 0, v2 = 0, v3 = 0;
    if (idx < NN) {
        int4 d = *(const int4*)(d_deg + idx);
        v0 = d.x - 1; v1 = d.y - 1; v2 = d.z - 1; v3 = d.w - 1;
    }
    int s = v0 + v1 + v2 + v3;
    tsum[t] = s;
    __syncthreads();
#pragma unroll
    for (int off = 1; off < 256; off <<= 1) {
        int a = (t >= off) ? tsum[t - off] : 0;
        __syncthreads();
        tsum[t] += a;
        __syncthreads();
    }
    if (idx < NN) {
        int run = d_blockoff[blockIdx.x] + tsum[t] - s;
        int4 ro = make_int4(run, run + v0, run + v0 + v1, run + v0 + v1 + v2);
        *(int4*)(d_rowoff  + idx) = ro;
        *(int4*)(d_fillpos + idx) = ro;
    }
}

__global__ void k_fill(const int* __restrict__ ei) {
    int e = blockIdx.x * blockDim.x + threadIdx.x;
    if (e >= EE) return;
    int s = ei[e];
    int d = ei[EE + e];
    int p = atomicAdd(&d_fillpos[d], 1);
    d_csrc[p] = s;
}

// ---------------- tf32 helpers --------------------------------------------------
__device__ __forceinline__ uint32_t f2tf32(float x) {
    uint32_t r;
    asm("cvt.rna.tf32.f32 %0, %1;" : "=r"(r) : "f"(x));
    return r;
}
__device__ __forceinline__ uint2 split_tf32(float x) {
    uint32_t hi = f2tf32(x);
    uint32_t lo = f2tf32(x - __uint_as_float(hi));
    return make_uint2(hi, lo);
}
__device__ __forceinline__ void mma_tf32(float* c, const uint32_t* a,
                                         uint32_t b0, uint32_t b1) {
    asm volatile(
        "mma.sync.aligned.m16n8k8.row.col.f32.tf32.tf32.f32 "
        "{%0,%1,%2,%3},{%4,%5,%6,%7},{%8,%9},{%0,%1,%2,%3};"
        : "+f"(c[0]), "+f"(c[1]), "+f"(c[2]), "+f"(c[3])
        : "r"(a[0]), "r"(a[1]), "r"(a[2]), "r"(a[3]), "r"(b0), "r"(b1));
}

// pre-split W[K][64] -> Whl[n][k] (tf32 hi/lo)
__global__ void k_prepW(const float* __restrict__ W, uint2* __restrict__ out, int K) {
    int idx = blockIdx.x * blockDim.x + threadIdx.x;
    if (idx >= K * 64) return;
    int k = idx >> 6, n = idx & 63;
    out[n * K + k] = split_tf32(W[idx]);
}

// ---------------- tensor-core GEMM: [nrows,K] @ [K,64] -> [nrows,64] -----------
// Block tile 128x64, 8 warps as 4 row-groups x 2 col-groups; warp tile 32x32.
// A: raw floats in smem, split to tf32 hi/lo inline (2 frags/warp/kk).
// B: pre-split uint2 from global (zero inner-loop CVTs).
// 3xTF32 compensation: lo*hi + hi*lo + hi*hi.
#define KC 32
#define SPADA 36     // float stride; (36*lg + lk) % 32 distinct per quad-pattern
#define SPADB 36     // uint2 stride; 72 banks == 8 mod 32, conflict-free LDS.64
template <int K, bool BN>
__global__ void __launch_bounds__(256, 3)
k_gemmTC(const float* __restrict__ A, const uint2* __restrict__ Whl,
         float* __restrict__ out, int nrows,
         const float* __restrict__ sumv, const float* __restrict__ sqv,
         const float* __restrict__ g, const float* __restrict__ be)
{
    __shared__ __align__(16) float sA[128 * SPADA];   // 18.4 KB
    __shared__ __align__(16) uint2 sB[64 * SPADB];    // 18.4 KB
    __shared__ float bnA[64], bnB[64];

    int tid  = threadIdx.x;
    int lane = tid & 31;
    int wid  = tid >> 5;
    int lg = lane >> 2;
    int lk = lane & 3;
    int row0 = blockIdx.x * 128;
    int wrow = (wid & 3) * 32;
    int wcol = (wid >> 2) * 32;

    if (BN) {
        if (tid < 64) {
            float mu  = sumv[tid] * (1.0f / NN);
            float var = sqv[tid] * (1.0f / NN) - mu * mu;
            float a = g[tid] * rsqrtf(var + BN_EPSF);
            bnA[tid] = a;
            bnB[tid] = be[tid] - mu * a;
        }
        __syncthreads();
    }

    float C[2][4][4];
#pragma unroll
    for (int mi = 0; mi < 2; mi++)
#pragma unroll
        for (int ni = 0; ni < 4; ni++)
#pragma unroll
            for (int j = 0; j < 4; j++) C[mi][ni][j] = 0.f;

    for (int kc = 0; kc < K; kc += KC) {
        // stage A: 128 rows x 32 k floats = 1024 float4, 4 per thread
#pragma unroll
        for (int it = 0; it < 4; it++) {
            int f4 = it * 256 + tid;
            int r  = f4 >> 3;
            int c4 = (f4 & 7) * 4;
            float4 v = make_float4(0.f, 0.f, 0.f, 0.f);
            if (row0 + r < nrows)
                v = *(const float4*)(A + (size_t)(row0 + r) * K + kc + c4);
            if (BN) {
                int c = kc + c4;
                v.x = fmaxf(fmaf(v.x, bnA[c + 0], bnB[c + 0]), 0.f);
                v.y = fmaxf(fmaf(v.y, bnA[c + 1], bnB[c + 1]), 0.f);
                v.z = fmaxf(fmaf(v.z, bnA[c + 2], bnB[c + 2]), 0.f);
                v.w = fmaxf(fmaf(v.w, bnA[c + 3], bnB[c + 3]), 0.f);
            }
            *(float4*)(sA + r * SPADA + c4) = v;      // 16B aligned (144B row)
        }
        // stage B: 64 n x 32 k uint2 = 1024 uint4, 4 per thread (pure copy)
#pragma unroll
        for (int it = 0; it < 4; it++) {
            int idx = it * 256 + tid;
            int n  = idx >> 4;
            int kp = (idx & 15) * 2;
            uint4 v = *(const uint4*)(Whl + (size_t)n * K + kc + kp);
            *(uint4*)(sB + n * SPADB + kp) = v;
        }
        __syncthreads();

#pragma unroll
        for (int kk = 0; kk < KC; kk += 8) {
            uint32_t ahi[2][4], alo[2][4];
#pragma unroll
            for (int mi = 0; mi < 2; mi++) {
                int rb = (wrow + mi * 16 + lg) * SPADA + kk + lk;
                float f0 = sA[rb];
                float f1 = sA[rb + 8 * SPADA];
                float f2 = sA[rb + 4];
                float f3 = sA[rb + 8 * SPADA + 4];
                ahi[mi][0] = f2tf32(f0); alo[mi][0] = f2tf32(f0 - __uint_as_float(ahi[mi][0]));
                ahi[mi][1] = f2tf32(f1); alo[mi][1] = f2tf32(f1 - __uint_as_float(ahi[mi][1]));
                ahi[mi][2] = f2tf32(f2); alo[mi][2] = f2tf32(f2 - __uint_as_float(ahi[mi][2]));
                ahi[mi][3] = f2tf32(f3); alo[mi][3] = f2tf32(f3 - __uint_as_float(ahi[mi][3]));
            }
#pragma unroll
            for (int ni = 0; ni < 4; ni++) {
                int nb = (wcol + ni * 8 + lg) * SPADB + kk + lk;
                uint2 b0 = sB[nb];
                uint2 b1 = sB[nb + 4];
#pragma unroll
                for (int mi = 0; mi < 2; mi++) {
                    mma_tf32(C[mi][ni], alo[mi], b0.x, b1.x);
                    mma_tf32(C[mi][ni], ahi[mi], b0.y, b1.y);
                    mma_tf32(C[mi][ni], ahi[mi], b0.x, b1.x);
                }
            }
        }
        __syncthreads();
    }

#pragma unroll
    for (int mi = 0; mi < 2; mi++) {
        int r0 = row0 + wrow + mi * 16 + lg;
        int r1 = r0 + 8;
#pragma unroll
        for (int ni = 0; ni < 4; ni++) {
            int col = wcol + ni * 8 + 2 * lk;
            if (r0 < nrows)
                *(float2*)(out + (size_t)r0 * 64 + col) = make_float2(C[mi][ni][0], C[mi][ni][1]);
            if (r1 < nrows)
                *(float2*)(out + (size_t)r1 * 64 + col) = make_float2(C[mi][ni][2], C[mi][ni][3]);
        }
    }
}

// ---------------- aggregation (pull, CSR by dst) + bias + fused BN stats -------
__global__ void k_agg64(const float* __restrict__ ht, const float* __restrict__ bias,
                        float* __restrict__ out,
                        float* __restrict__ sumv, float* __restrict__ sqv)
{
    __shared__ float s_s[8 * 64];
    __shared__ float s_q[8 * 64];
    int warp = (blockIdx.x * blockDim.x + threadIdx.x) >> 5;
    int w    = threadIdx.x >> 5;
    int lane = threadIdx.x & 31;
    int c0   = lane * 2;
    float acc0 = 0.f, acc1 = 0.f;
    if (warp < NN) {
        const int i = warp;
        float di = d_dinv[i];
        float2 sv = *(const float2*)(ht + i * 64 + c0);
        acc0 = di * di * sv.x;
        acc1 = di * di * sv.y;
        int e0 = d_rowoff[i], e1 = d_rowoff[i + 1];
        for (int j0 = e0; j0 < e1; j0 += 32) {
            int j = j0 + lane;
            int src = 0; float dv = 0.f;
            if (j < e1) { src = d_csrc[j]; dv = __ldg(&d_dinv[src]); }
            int cnt = min(32, e1 - j0);
#pragma unroll 4
            for (int k = 0; k < cnt; k++) {
                int   sk = __shfl_sync(0xffffffffu, src, k);
                float wk = __shfl_sync(0xffffffffu, dv, k) * di;
                float2 hv = __ldg((const float2*)(ht + sk * 64 + c0));
                acc0 = fmaf(wk, hv.x, acc0);
                acc1 = fmaf(wk, hv.y, acc1);
            }
        }
        acc0 += bias[c0];
        acc1 += bias[c0 + 1];
        *(float2*)(out + i * 64 + c0) = make_float2(acc0, acc1);
    }
    s_s[w * 64 + c0]     = acc0;
    s_s[w * 64 + c0 + 1] = acc1;
    s_q[w * 64 + c0]     = acc0 * acc0;
    s_q[w * 64 + c0 + 1] = acc1 * acc1;
    __syncthreads();
    if (threadIdx.x < 64) {
        float ss = 0.f, qs = 0.f;
#pragma unroll
        for (int r = 0; r < 8; r++) {
            ss += s_s[r * 64 + threadIdx.x];
            qs += s_q[r * 64 + threadIdx.x];
        }
        atomicAdd(&sumv[threadIdx.x], ss);
        atomicAdd(&sqv[threadIdx.x], qs);
    }
}

// ---------------- layer 3: BN+ReLU inline, [N,64]@[64,3] -----------------------
__global__ void k_gemm3(const float* __restrict__ h, const float* __restrict__ W3,
                        float* __restrict__ out,
                        const float* __restrict__ sumv, const float* __restrict__ sqv,
                        const float* __restrict__ g, const float* __restrict__ be)
{
    __shared__ float wsh[DH * DOUT];
    __shared__ float bnA[64], bnB[64];
    if (threadIdx.x < DH * DOUT) wsh[threadIdx.x] = W3[threadIdx.x];
    if (threadIdx.x < 64) {
        float mu  = sumv[threadIdx.x] * (1.0f / NN);
        float var = sqv[threadIdx.x] * (1.0f / NN) - mu * mu;
        float a = g[threadIdx.x] * rsqrtf(var + BN_EPSF);
        bnA[threadIdx.x] = a;
        bnB[threadIdx.x] = be[threadIdx.x] - mu * a;
    }
    __syncthreads();
    int i = blockIdx.x * blockDim.x + threadIdx.x;
    if (i >= NN) return;
    float a0 = 0.f, a1 = 0.f, a2 = 0.f;
    const float4* hp = (const float4*)(h + (size_t)i * DH);
#pragma unroll
    for (int q4 = 0; q4 < 16; q4++) {
        float4 v = hp[q4];
        int k = q4 * 4;
        float e0 = fmaxf(fmaf(v.x, bnA[k + 0], bnB[k + 0]), 0.f);
        float e1 = fmaxf(fmaf(v.y, bnA[k + 1], bnB[k + 1]), 0.f);
        float e2 = fmaxf(fmaf(v.z, bnA[k + 2], bnB[k + 2]), 0.f);
        float e3 = fmaxf(fmaf(v.w, bnA[k + 3], bnB[k + 3]), 0.f);
        a0 = fmaf(e0, wsh[(k + 0) * 3 + 0], a0); a1 = fmaf(e0, wsh[(k + 0) * 3 + 1], a1); a2 = fmaf(e0, wsh[(k + 0) * 3 + 2], a2);
        a0 = fmaf(e1, wsh[(k + 1) * 3 + 0], a0); a1 = fmaf(e1, wsh[(k + 1) * 3 + 1], a1); a2 = fmaf(e1, wsh[(k + 1) * 3 + 2], a2);
        a0 = fmaf(e2, wsh[(k + 2) * 3 + 0], a0); a1 = fmaf(e2, wsh[(k + 2) * 3 + 1], a1); a2 = fmaf(e2, wsh[(k + 2) * 3 + 2], a2);
        a0 = fmaf(e3, wsh[(k + 3) * 3 + 0], a0); a1 = fmaf(e3, wsh[(k + 3) * 3 + 1], a1); a2 = fmaf(e3, wsh[(k + 3) * 3 + 2], a2);
    }
    out[i * 3 + 0] = a0; out[i * 3 + 1] = a1; out[i * 3 + 2] = a2;
}

__global__ void k_agg3(const float* __restrict__ ht, const float* __restrict__ b3,
                       float* __restrict__ out)
{
    int i = blockIdx.x * blockDim.x + threadIdx.x;
    if (i >= NN) return;
    float di = d_dinv[i], ws = di * di;
    float a0 = ws * ht[i * 3 + 0];
    float a1 = ws * ht[i * 3 + 1];
    float a2 = ws * ht[i * 3 + 2];
    int e1 = d_rowoff[i + 1];
    for (int j = d_rowoff[i]; j < e1; j++) {
        int s = d_csrc[j];
        float w = __ldg(&d_dinv[s]) * di;
        a0 = fmaf(w, ht[s * 3 + 0], a0);
        a1 = fmaf(w, ht[s * 3 + 1], a1);
        a2 = fmaf(w, ht[s * 3 + 2], a2);
    }
    out[i * 3 + 0] = a0 + b3[0];
    out[i * 3 + 1] = a1 + b3[1];
    out[i * 3 + 2] = a2 + b3[2];
}

// ---------------- pooling + log_softmax ----------------------------------------
__global__ void k_pool(const float* __restrict__ h3, const int* __restrict__ batch)
{
    __shared__ float sh[NG * 4];
    if (threadIdx.x < NG * 4) sh[threadIdx.x] = 0.f;
    __syncthreads();
    int i = blockIdx.x * blockDim.x + threadIdx.x;
    if (i < NN) {
        int g = batch[i];
        atomicAdd(&sh[g * 4 + 0], h3[i * 3 + 0]);
        atomicAdd(&sh[g * 4 + 1], h3[i * 3 + 1]);
        atomicAdd(&sh[g * 4 + 2], h3[i * 3 + 2]);
        atomicAdd(&sh[g * 4 + 3], 1.0f);
    }
    __syncthreads();
    if (threadIdx.x < NG * 4 && sh[threadIdx.x] != 0.f)
        atomicAdd(&d_pool[threadIdx.x], sh[threadIdx.x]);
}

__global__ void k_final(float* __restrict__ out)
{
    int g = threadIdx.x;
    if (g >= NG) return;
    float cnt = fmaxf(d_pool[g * 4 + 3], 1.0f);
    float v0 = d_pool[g * 4 + 0] / cnt;
    float v1 = d_pool[g * 4 + 1] / cnt;
    float v2 = d_pool[g * 4 + 2] / cnt;
    float m = fmaxf(v0, fmaxf(v1, v2));
    float l = m + logf(expf(v0 - m) + expf(v1 - m) + expf(v2 - m));
    out[g * 3 + 0] = v0 - l;
    out[g * 3 + 1] = v1 - l;
    out[g * 3 + 2] = v2 - l;
}

// ---------------- launch --------------------------------------------------------
extern "C" void kernel_launch(void* const* d_in, const int* in_sizes, int n_in,
                              void* d_out, int out_size)
{
    const float* x    = (const float*)d_in[0];
    const int*   ei   = (const int*)d_in[1];
    const int*   batch= (const int*)d_in[2];
    const float* W1   = (const float*)d_in[3];
    const float* b1   = (const float*)d_in[4];
    const float* g1   = (const float*)d_in[5];
    const float* be1  = (const float*)d_in[6];
    const float* W2   = (const float*)d_in[7];
    const float* b2   = (const float*)d_in[8];
    const float* g2   = (const float*)d_in[9];
    const float* be2  = (const float*)d_in[10];
    const float* W3   = (const float*)d_in[11];
    const float* b3   = (const float*)d_in[12];
    float* out = (float*)d_out;

    float *bufT, *bufA, *h3t, *h3, *sum1, *sq1, *sum2, *sq2;
    uint2 *w1hl, *w2hl;
    cudaGetSymbolAddress((void**)&bufT, d_bufT);
    cudaGetSymbolAddress((void**)&bufA, d_bufA);
    cudaGetSymbolAddress((void**)&h3t,  d_h3t);
    cudaGetSymbolAddress((void**)&h3,   d_h3);
    cudaGetSymbolAddress((void**)&sum1, d_sum1);
    cudaGetSymbolAddress((void**)&sq1,  d_sq1);
    cudaGetSymbolAddress((void**)&sum2, d_sum2);
    cudaGetSymbolAddress((void**)&sq2,  d_sq2);
    cudaGetSymbolAddress((void**)&w1hl, d_W1hl);
    cudaGetSymbolAddress((void**)&w2hl, d_W2hl);

    static cudaStream_t s2 = 0;
    static cudaEvent_t evFork = 0, evJoin = 0;
    if (s2 == 0) {
        cudaStreamCreateWithFlags(&s2, cudaStreamNonBlocking);
        cudaEventCreateWithFlags(&evFork, cudaEventDisableTiming);
        cudaEventCreateWithFlags(&evJoin, cudaEventDisableTiming);
    }

    const int TB = 256;
    int gN = (NN + TB - 1) / TB;
    int gE = (EE + TB - 1) / TB;
    int gTC = (NN + 127) / 128;

    // fork: s2 runs W prep + GEMM1 overlapped with the structure build
    cudaEventRecord(evFork, 0);
    cudaStreamWaitEvent(s2, evFork, 0);

    k_init<<<gN, TB>>>();                                            // 1
    k_prepW<<<(DIN * 64 + TB - 1) / TB, TB, 0, s2>>>(W1, w1hl, DIN); // 2
    k_prepW<<<(DH * 64 + TB - 1) / TB, TB, 0, s2>>>(W2, w2hl, DH);   // 3
    k_gemmTC<DIN, false><<<gTC, 256, 0, s2>>>(x, w1hl, bufT, NN,     // 4 (ncu slot)
                                              0, 0, 0, 0);
    cudaEventRecord(evJoin, s2);

    k_hist<<<gE, TB>>>(ei);
    k_partial<<<NBLK, 256>>>();
    k_scanblock<<<1, 128>>>();
    k_scatter<<<NBLK, 256>>>();
    k_fill<<<gE, TB>>>(ei);

    cudaStreamWaitEvent(0, evJoin, 0);

    // layer 1 aggregation (+bias +BN stats)
    k_agg64<<<(NN * 32 + TB - 1) / TB, TB>>>(bufT, b1, bufA, sum1, sq1);

    // layer 2: tensor-core GEMM, BN+ReLU fused into A staging
    k_gemmTC<DH, true><<<gTC, 256>>>(bufA, w2hl, bufT, NN, sum1, sq1, g1, be1);
    k_agg64<<<(NN * 32 + TB - 1) / TB, TB>>>(bufT, b2, bufA, sum2, sq2);

    // layer 3
    k_gemm3<<<gN, TB>>>(bufA, W3, h3t, sum2, sq2, g2, be2);
    k_agg3<<<gN, TB>>>(h3t, b3, h3);
    k_pool<<<gN, TB>>>(h3, batch);
    k_final<<<1, 64>>>(out);
}

// round 12
// speedup vs baseline: 1.2350x; 1.1466x over previous
#include <cuda_runtime.h>
#include <math.h>
#include <stdint.h>

#define NN 100000
#define EE 1600000
#define DIN 256
#define DH 64
#define DOUT 3
#define NG 64
#define BN_EPSF 1e-5f

#define SCAN_ELEMS 1024
#define NBLK ((NN + SCAN_ELEMS - 1) / SCAN_ELEMS)   // 98

// ---------------- scratch (device globals; no allocation allowed) -------------
__device__ int    d_deg[NN];
__device__ __align__(16) float d_dinv[NN];
__device__ int    d_rowoff[NN + 1];
__device__ int    d_fillpos[NN];
__device__ int    d_blocksum[NBLK];
__device__ int    d_blockoff[NBLK];
__device__ int    d_csrc[EE];
__device__ __align__(16) float d_bufT[(size_t)NN * DH];
__device__ __align__(16) float d_bufA[(size_t)NN * DH];
__device__ __align__(16) float d_h3t[NN * DOUT + 4];
__device__ __align__(16) float d_h3[NN * DOUT + 4];
__device__ float  d_sum1[DH], d_sq1[DH], d_sum2[DH], d_sq2[DH];
__device__ float  d_pool[NG * 4];
__device__ __align__(16) uint32_t d_W1h[64 * DIN];   // [n][k] tf32 hi
__device__ __align__(16) uint32_t d_W2h[64 * DH];

// ---------------- structure build ---------------------------------------------
__global__ void k_init() {
    int i = blockIdx.x * blockDim.x + threadIdx.x;
    if (i < NN) d_deg[i] = 1;
    if (i < DH) { d_sum1[i] = 0.f; d_sq1[i] = 0.f; d_sum2[i] = 0.f; d_sq2[i] = 0.f; }
    if (i < NG * 4) d_pool[i] = 0.f;
}

__global__ void k_hist(const int* __restrict__ ei) {
    int e = blockIdx.x * blockDim.x + threadIdx.x;
    if (e < EE) atomicAdd(&d_deg[ei[EE + e]], 1);
}

__global__ void k_partial() {
    int t = threadIdx.x;
    int idx = blockIdx.x * SCAN_ELEMS + t * 4;
    int s = 0;
    if (idx < NN) {
        int4 d = *(const int4*)(d_deg + idx);
        s = d.x + d.y + d.z + d.w - 4;
        float4 r;
        r.x = rsqrtf((float)d.x);
        r.y = rsqrtf((float)d.y);
        r.z = rsqrtf((float)d.z);
        r.w = rsqrtf((float)d.w);
        *(float4*)(d_dinv + idx) = r;
    }
    __shared__ int sh[8];
#pragma unroll
    for (int o = 16; o; o >>= 1) s += __shfl_down_sync(0xffffffffu, s, o);
    if ((t & 31) == 0) sh[t >> 5] = s;
    __syncthreads();
    if (t < 32) {
        int v = (t < 8) ? sh[t] : 0;
#pragma unroll
        for (int o = 4; o; o >>= 1) v += __shfl_down_sync(0xffffffffu, v, o);
        if (t == 0) d_blocksum[blockIdx.x] = v;
    }
}

__global__ void k_scanblock() {
    __shared__ int sh[128];
    int t = threadIdx.x;
    int v = (t < NBLK) ? d_blocksum[t] : 0;
    sh[t] = v;
    __syncthreads();
#pragma unroll
    for (int off = 1; off < 128; off <<= 1) {
        int a = (t >= off) ? sh[t - off] : 0;
        __syncthreads();
        sh[t] += a;
        __syncthreads();
    }
    if (t < NBLK) d_blockoff[t] = sh[t] - v;
    if (t == 127) d_rowoff[NN] = sh[127];
}

__global__ void k_scatter() {
    __shared__ int tsum[256];
    int t = threadIdx.x;
    int idx = blockIdx.x * SCAN_ELEMS + t * 4;
    int v0 = 0, v1 = 0, v2 = 0, v3 = 0;
    if (idx < NN) {
        int4 d = *(const int4*)(d_deg + idx);
        v0 = d.x - 1; v1 = d.y - 1; v2 = d.z - 1; v3 = d.w - 1;
    }
    int s = v0 + v1 + v2 + v3;
    tsum[t] = s;
    __syncthreads();
#pragma unroll
    for (int off = 1; off < 256; off <<= 1) {
        int a = (t >= off) ? tsum[t - off] : 0;
        __syncthreads();
        tsum[t] += a;
        __syncthreads();
    }
    if (idx < NN) {
        int run = d_blockoff[blockIdx.x] + tsum[t] - s;
        int4 ro = make_int4(run, run + v0, run + v0 + v1, run + v0 + v1 + v2);
        *(int4*)(d_rowoff  + idx) = ro;
        *(int4*)(d_fillpos + idx) = ro;
    }
}

__global__ void k_fill(const int* __restrict__ ei) {
    int e = blockIdx.x * blockDim.x + threadIdx.x;
    if (e >= EE) return;
    int s = ei[e];
    int d = ei[EE + e];
    int p = atomicAdd(&d_fillpos[d], 1);
    d_csrc[p] = s;
}

// ---------------- tf32 helpers --------------------------------------------------
__device__ __forceinline__ uint32_t f2tf32(float x) {
    uint32_t r;
    asm("cvt.rna.tf32.f32 %0, %1;" : "=r"(r) : "f"(x));
    return r;
}
__device__ __forceinline__ void mma_tf32(float* c, const uint32_t* a,
                                         uint32_t b0, uint32_t b1) {
    asm volatile(
        "mma.sync.aligned.m16n8k8.row.col.f32.tf32.tf32.f32 "
        "{%0,%1,%2,%3},{%4,%5,%6,%7},{%8,%9},{%0,%1,%2,%3};"
        : "+f"(c[0]), "+f"(c[1]), "+f"(c[2]), "+f"(c[3])
        : "r"(a[0]), "r"(a[1]), "r"(a[2]), "r"(a[3]), "r"(b0), "r"(b1));
}

// pre-convert W[K][64] -> Wt[n][k] (tf32 hi only)
__global__ void k_prepW(const float* __restrict__ W, uint32_t* __restrict__ out, int K) {
    int idx = blockIdx.x * blockDim.x + threadIdx.x;
    if (idx >= K * 64) return;
    int k = idx >> 6, n = idx & 63;
    out[n * K + k] = f2tf32(W[idx]);
}

// ---------------- tensor-core GEMM: [nrows,K] @ [K,64] -> [nrows,64] -----------
// Block tile 128x64, 8 warps as 4 row-groups x 2 col-groups; warp tile 32x32.
// 1xTF32: A converted to tf32 at staging, B pre-converted globally.
// Inner loop is pure LDS + MMA (zero CVTs, zero splits).
#define KC 32
#define SPADA 36
#define SPADB 36
template <int K, bool BN>
__global__ void __launch_bounds__(256, 3)
k_gemmTC(const float* __restrict__ A, const uint32_t* __restrict__ Wt,
         float* __restrict__ out, int nrows,
         const float* __restrict__ sumv, const float* __restrict__ sqv,
         const float* __restrict__ g, const float* __restrict__ be)
{
    __shared__ __align__(16) uint32_t sA[128 * SPADA];   // 18.4 KB (tf32 bits)
    __shared__ __align__(16) uint32_t sB[64 * SPADB];    // 9.2 KB
    __shared__ float bnA[64], bnB[64];

    int tid  = threadIdx.x;
    int lane = tid & 31;
    int wid  = tid >> 5;
    int lg = lane >> 2;
    int lk = lane & 3;
    int row0 = blockIdx.x * 128;
    int wrow = (wid & 3) * 32;
    int wcol = (wid >> 2) * 32;

    if (BN) {
        if (tid < 64) {
            float mu  = sumv[tid] * (1.0f / NN);
            float var = sqv[tid] * (1.0f / NN) - mu * mu;
            float a = g[tid] * rsqrtf(var + BN_EPSF);
            bnA[tid] = a;
            bnB[tid] = be[tid] - mu * a;
        }
        __syncthreads();
    }

    float C[2][4][4];
#pragma unroll
    for (int mi = 0; mi < 2; mi++)
#pragma unroll
        for (int ni = 0; ni < 4; ni++)
#pragma unroll
            for (int j = 0; j < 4; j++) C[mi][ni][j] = 0.f;

    for (int kc = 0; kc < K; kc += KC) {
        // stage A: 128 rows x 32 k = 1024 float4, 4/thread; cvt to tf32 here
#pragma unroll
        for (int it = 0; it < 4; it++) {
            int f4 = it * 256 + tid;
            int r  = f4 >> 3;
            int c4 = (f4 & 7) * 4;
            float4 v = make_float4(0.f, 0.f, 0.f, 0.f);
            if (row0 + r < nrows)
                v = *(const float4*)(A + (size_t)(row0 + r) * K + kc + c4);
            if (BN) {
                int c = kc + c4;
                v.x = fmaxf(fmaf(v.x, bnA[c + 0], bnB[c + 0]), 0.f);
                v.y = fmaxf(fmaf(v.y, bnA[c + 1], bnB[c + 1]), 0.f);
                v.z = fmaxf(fmaf(v.z, bnA[c + 2], bnB[c + 2]), 0.f);
                v.w = fmaxf(fmaf(v.w, bnA[c + 3], bnB[c + 3]), 0.f);
            }
            uint4 u;
            u.x = f2tf32(v.x); u.y = f2tf32(v.y);
            u.z = f2tf32(v.z); u.w = f2tf32(v.w);
            *(uint4*)(sA + r * SPADA + c4) = u;
        }
        // stage B: 64 n x 32 k uint = 512 uint4, 2/thread (pure copy)
#pragma unroll
        for (int it = 0; it < 2; it++) {
            int f4 = it * 256 + tid;
            int n  = f4 >> 3;
            int kp = (f4 & 7) * 4;
            uint4 v = *(const uint4*)(Wt + (size_t)n * K + kc + kp);
            *(uint4*)(sB + n * SPADB + kp) = v;
        }
        __syncthreads();

#pragma unroll
        for (int kk = 0; kk < KC; kk += 8) {
            uint32_t a[2][4];
#pragma unroll
            for (int mi = 0; mi < 2; mi++) {
                int rb = (wrow + mi * 16 + lg) * SPADA + kk + lk;
                a[mi][0] = sA[rb];
                a[mi][1] = sA[rb + 8 * SPADA];
                a[mi][2] = sA[rb + 4];
                a[mi][3] = sA[rb + 8 * SPADA + 4];
            }
#pragma unroll
            for (int ni = 0; ni < 4; ni++) {
                int nb = (wcol + ni * 8 + lg) * SPADB + kk + lk;
                uint32_t b0 = sB[nb];
                uint32_t b1 = sB[nb + 4];
                mma_tf32(C[0][ni], a[0], b0, b1);
                mma_tf32(C[1][ni], a[1], b0, b1);
            }
        }
        __syncthreads();
    }

#pragma unroll
    for (int mi = 0; mi < 2; mi++) {
        int r0 = row0 + wrow + mi * 16 + lg;
        int r1 = r0 + 8;
#pragma unroll
        for (int ni = 0; ni < 4; ni++) {
            int col = wcol + ni * 8 + 2 * lk;
            if (r0 < nrows)
                *(float2*)(out + (size_t)r0 * 64 + col) = make_float2(C[mi][ni][0], C[mi][ni][1]);
            if (r1 < nrows)
                *(float2*)(out + (size_t)r1 * 64 + col) = make_float2(C[mi][ni][2], C[mi][ni][3]);
        }
    }
}

// ---------------- aggregation (pull, CSR by dst) + bias + fused BN stats -------
__global__ void k_agg64(const float* __restrict__ ht, const float* __restrict__ bias,
                        float* __restrict__ out,
                        float* __restrict__ sumv, float* __restrict__ sqv)
{
    __shared__ float s_s[8 * 64];
    __shared__ float s_q[8 * 64];
    int warp = (blockIdx.x * blockDim.x + threadIdx.x) >> 5;
    int w    = threadIdx.x >> 5;
    int lane = threadIdx.x & 31;
    int c0   = lane * 2;
    float acc0 = 0.f, acc1 = 0.f;
    if (warp < NN) {
        const int i = warp;
        float di = d_dinv[i];
        float2 sv = *(const float2*)(ht + i * 64 + c0);
        acc0 = di * di * sv.x;
        acc1 = di * di * sv.y;
        int e0 = d_rowoff[i], e1 = d_rowoff[i + 1];
        for (int j0 = e0; j0 < e1; j0 += 32) {
            int j = j0 + lane;
            int src = 0; float dv = 0.f;
            if (j < e1) { src = d_csrc[j]; dv = __ldg(&d_dinv[src]); }
            int cnt = min(32, e1 - j0);
#pragma unroll 4
            for (int k = 0; k < cnt; k++) {
                int   sk = __shfl_sync(0xffffffffu, src, k);
                float wk = __shfl_sync(0xffffffffu, dv, k) * di;
                float2 hv = __ldg((const float2*)(ht + sk * 64 + c0));
                acc0 = fmaf(wk, hv.x, acc0);
                acc1 = fmaf(wk, hv.y, acc1);
            }
        }
        acc0 += bias[c0];
        acc1 += bias[c0 + 1];
        *(float2*)(out + i * 64 + c0) = make_float2(acc0, acc1);
    }
    s_s[w * 64 + c0]     = acc0;
    s_s[w * 64 + c0 + 1] = acc1;
    s_q[w * 64 + c0]     = acc0 * acc0;
    s_q[w * 64 + c0 + 1] = acc1 * acc1;
    __syncthreads();
    if (threadIdx.x < 64) {
        float ss = 0.f, qs = 0.f;
#pragma unroll
        for (int r = 0; r < 8; r++) {
            ss += s_s[r * 64 + threadIdx.x];
            qs += s_q[r * 64 + threadIdx.x];
        }
        atomicAdd(&sumv[threadIdx.x], ss);
        atomicAdd(&sqv[threadIdx.x], qs);
    }
}

// ---------------- layer 3: BN+ReLU inline, [N,64]@[64,3] -----------------------
__global__ void k_gemm3(const float* __restrict__ h, const float* __restrict__ W3,
                        float* __restrict__ out,
                        const float* __restrict__ sumv, const float* __restrict__ sqv,
                        const float* __restrict__ g, const float* __restrict__ be)
{
    __shared__ float wsh[DH * DOUT];
    __shared__ float bnA[64], bnB[64];
    if (threadIdx.x < DH * DOUT) wsh[threadIdx.x] = W3[threadIdx.x];
    if (threadIdx.x < 64) {
        float mu  = sumv[threadIdx.x] * (1.0f / NN);
        float var = sqv[threadIdx.x] * (1.0f / NN) - mu * mu;
        float a = g[threadIdx.x] * rsqrtf(var + BN_EPSF);
        bnA[threadIdx.x] = a;
        bnB[threadIdx.x] = be[threadIdx.x] - mu * a;
    }
    __syncthreads();
    int i = blockIdx.x * blockDim.x + threadIdx.x;
    if (i >= NN) return;
    float a0 = 0.f, a1 = 0.f, a2 = 0.f;
    const float4* hp = (const float4*)(h + (size_t)i * DH);
#pragma unroll
    for (int q4 = 0; q4 < 16; q4++) {
        float4 v = hp[q4];
        int k = q4 * 4;
        float e0 = fmaxf(fmaf(v.x, bnA[k + 0], bnB[k + 0]), 0.f);
        float e1 = fmaxf(fmaf(v.y, bnA[k + 1], bnB[k + 1]), 0.f);
        float e2 = fmaxf(fmaf(v.z, bnA[k + 2], bnB[k + 2]), 0.f);
        float e3 = fmaxf(fmaf(v.w, bnA[k + 3], bnB[k + 3]), 0.f);
        a0 = fmaf(e0, wsh[(k + 0) * 3 + 0], a0); a1 = fmaf(e0, wsh[(k + 0) * 3 + 1], a1); a2 = fmaf(e0, wsh[(k + 0) * 3 + 2], a2);
        a0 = fmaf(e1, wsh[(k + 1) * 3 + 0], a0); a1 = fmaf(e1, wsh[(k + 1) * 3 + 1], a1); a2 = fmaf(e1, wsh[(k + 1) * 3 + 2], a2);
        a0 = fmaf(e2, wsh[(k + 2) * 3 + 0], a0); a1 = fmaf(e2, wsh[(k + 2) * 3 + 1], a1); a2 = fmaf(e2, wsh[(k + 2) * 3 + 2], a2);
        a0 = fmaf(e3, wsh[(k + 3) * 3 + 0], a0); a1 = fmaf(e3, wsh[(k + 3) * 3 + 1], a1); a2 = fmaf(e3, wsh[(k + 3) * 3 + 2], a2);
    }
    out[i * 3 + 0] = a0; out[i * 3 + 1] = a1; out[i * 3 + 2] = a2;
}

__global__ void k_agg3(const float* __restrict__ ht, const float* __restrict__ b3,
                       float* __restrict__ out)
{
    int i = blockIdx.x * blockDim.x + threadIdx.x;
    if (i >= NN) return;
    float di = d_dinv[i], ws = di * di;
    float a0 = ws * ht[i * 3 + 0];
    float a1 = ws * ht[i * 3 + 1];
    float a2 = ws * ht[i * 3 + 2];
    int e1 = d_rowoff[i + 1];
    for (int j = d_rowoff[i]; j < e1; j++) {
        int s = d_csrc[j];
        float w = __ldg(&d_dinv[s]) * di;
        a0 = fmaf(w, ht[s * 3 + 0], a0);
        a1 = fmaf(w, ht[s * 3 + 1], a1);
        a2 = fmaf(w, ht[s * 3 + 2], a2);
    }
    out[i * 3 + 0] = a0 + b3[0];
    out[i * 3 + 1] = a1 + b3[1];
    out[i * 3 + 2] = a2 + b3[2];
}

// ---------------- pooling + log_softmax ----------------------------------------
__global__ void k_pool(const float* __restrict__ h3, const int* __restrict__ batch)
{
    __shared__ float sh[NG * 4];
    if (threadIdx.x < NG * 4) sh[threadIdx.x] = 0.f;
    __syncthreads();
    int i = blockIdx.x * blockDim.x + threadIdx.x;
    if (i < NN) {
        int g = batch[i];
        atomicAdd(&sh[g * 4 + 0], h3[i * 3 + 0]);
        atomicAdd(&sh[g * 4 + 1], h3[i * 3 + 1]);
        atomicAdd(&sh[g * 4 + 2], h3[i * 3 + 2]);
        atomicAdd(&sh[g * 4 + 3], 1.0f);
    }
    __syncthreads();
    if (threadIdx.x < NG * 4 && sh[threadIdx.x] != 0.f)
        atomicAdd(&d_pool[threadIdx.x], sh[threadIdx.x]);
}

__global__ void k_final(float* __restrict__ out)
{
    int g = threadIdx.x;
    if (g >= NG) return;
    float cnt = fmaxf(d_pool[g * 4 + 3], 1.0f);
    float v0 = d_pool[g * 4 + 0] / cnt;
    float v1 = d_pool[g * 4 + 1] / cnt;
    float v2 = d_pool[g * 4 + 2] / cnt;
    float m = fmaxf(v0, fmaxf(v1, v2));
    float l = m + logf(expf(v0 - m) + expf(v1 - m) + expf(v2 - m));
    out[g * 3 + 0] = v0 - l;
    out[g * 3 + 1] = v1 - l;
    out[g * 3 + 2] = v2 - l;
}

// ---------------- launch --------------------------------------------------------
extern "C" void kernel_launch(void* const* d_in, const int* in_sizes, int n_in,
                              void* d_out, int out_size)
{
    const float* x    = (const float*)d_in[0];
    const int*   ei   = (const int*)d_in[1];
    const int*   batch= (const int*)d_in[2];
    const float* W1   = (const float*)d_in[3];
    const float* b1   = (const float*)d_in[4];
    const float* g1   = (const float*)d_in[5];
    const float* be1  = (const float*)d_in[6];
    const float* W2   = (const float*)d_in[7];
    const float* b2   = (const float*)d_in[8];
    const float* g2   = (const float*)d_in[9];
    const float* be2  = (const float*)d_in[10];
    const float* W3   = (const float*)d_in[11];
    const float* b3   = (const float*)d_in[12];
    float* out = (float*)d_out;

    float *bufT, *bufA, *h3t, *h3, *sum1, *sq1, *sum2, *sq2;
    uint32_t *w1h, *w2h;
    cudaGetSymbolAddress((void**)&bufT, d_bufT);
    cudaGetSymbolAddress((void**)&bufA, d_bufA);
    cudaGetSymbolAddress((void**)&h3t,  d_h3t);
    cudaGetSymbolAddress((void**)&h3,   d_h3);
    cudaGetSymbolAddress((void**)&sum1, d_sum1);
    cudaGetSymbolAddress((void**)&sq1,  d_sq1);
    cudaGetSymbolAddress((void**)&sum2, d_sum2);
    cudaGetSymbolAddress((void**)&sq2,  d_sq2);
    cudaGetSymbolAddress((void**)&w1h,  d_W1h);
    cudaGetSymbolAddress((void**)&w2h,  d_W2h);

    static cudaStream_t s2 = 0;
    static cudaEvent_t evFork = 0, evJoin = 0;
    if (s2 == 0) {
        cudaStreamCreateWithFlags(&s2, cudaStreamNonBlocking);
        cudaEventCreateWithFlags(&evFork, cudaEventDisableTiming);
        cudaEventCreateWithFlags(&evJoin, cudaEventDisableTiming);
    }

    const int TB = 256;
    int gN = (NN + TB - 1) / TB;
    int gE = (EE + TB - 1) / TB;
    int gTC = (NN + 127) / 128;

    // fork: s2 runs W prep + GEMM1 overlapped with the structure build
    cudaEventRecord(evFork, 0);
    cudaStreamWaitEvent(s2, evFork, 0);

    k_init<<<gN, TB>>>();                                            // 1
    k_prepW<<<(DIN * 64 + TB - 1) / TB, TB, 0, s2>>>(W1, w1h, DIN);  // 2
    k_prepW<<<(DH * 64 + TB - 1) / TB, TB, 0, s2>>>(W2, w2h, DH);    // 3
    k_gemmTC<DIN, false><<<gTC, 256, 0, s2>>>(x, w1h, bufT, NN,      // 4 (ncu slot)
                                              0, 0, 0, 0);
    cudaEventRecord(evJoin, s2);

    k_hist<<<gE, TB>>>(ei);
    k_partial<<<NBLK, 256>>>();
    k_scanblock<<<1, 128>>>();
    k_scatter<<<NBLK, 256>>>();
    k_fill<<<gE, TB>>>(ei);

    cudaStreamWaitEvent(0, evJoin, 0);

    // layer 1 aggregation (+bias +BN stats)
    k_agg64<<<(NN * 32 + TB - 1) / TB, TB>>>(bufT, b1, bufA, sum1, sq1);

    // layer 2: tensor-core GEMM, BN+ReLU fused into A staging
    k_gemmTC<DH, true><<<gTC, 256>>>(bufA, w2h, bufT, NN, sum1, sq1, g1, be1);
    k_agg64<<<(NN * 32 + TB - 1) / TB, TB>>>(bufT, b2, bufA, sum2, sq2);

    // layer 3
    k_gemm3<<<gN, TB>>>(bufA, W3, h3t, sum2, sq2, g2, be2);
    k_agg3<<<gN, TB>>>(h3t, b3, h3);
    k_pool<<<gN, TB>>>(h3, batch);
    k_final<<<1, 64>>>(out);
}